// round 3
// baseline (speedup 1.0000x reference)
#include <cuda_runtime.h>
#include <math.h>

// Problem constants
#define B      64
#define LS     256
#define MM     16
#define NSTEP  10
#define HH     1024
#define BM     1024           // B*MM rows
#define KW     512            // w_r|w_i contraction dim
#define NSEG   11             // 10 W1 steps + 1 V1
#define P_STRIDE (BM*HH)      // 1048576

#define N_SELEM (B*(NSTEP+1)*LS)     // 180224 complex elements

// ---- scratch (static __device__, allocation-free) ----
__device__ float g_P[NSEG * BM * HH];        // precomputed (w,y,bias) pre-activations
__device__ float g_Aw[BM * KW];              // transposed w: [row=b*16+m][k]
__device__ float g_W2T[NSTEP * LS * HH];     // W2 transposed: [s][l][k]
__device__ float g_yp[NSEG * MM * HH];       // y-part per (s,m,h)
__device__ float g_phi[B * LS];
__device__ float g_spart[B * 2048];          // [b][h] W1-path | [b][1024+h] V1-path
__device__ float g_g[B * HH];                // sum_m rho*h
__device__ float g_rhosum[B];

// Generic s-writer: idx = (b*(NSTEP+1)+t)*LS + l
__device__ __forceinline__ void write_s(float* out, int idx, float cv, float sv,
                                        int inter, int reOff, int imOff) {
    if (inter) {
        out[2 * idx]     = cv;
        out[2 * idx + 1] = sv;
    } else {
        out[reOff + idx] = cv;
        if (imOff >= 0) out[imOff + idx] = sv;
    }
}

// ============ precompute kernels (parallel, phi-independent) ============

// Aw[row=b*16+m][k] = k<256 ? w_r[b,k,m] : w_i[b,k-256,m]
__global__ void kTw(const float* __restrict__ wr, const float* __restrict__ wi) {
    int e = blockIdx.x * 256 + threadIdx.x;       // 524288 elements
    int row = e >> 9, k = e & 511;
    int b = row >> 4, m = row & 15;
    float v = (k < 256) ? wr[((size_t)b * 256 + k) * 16 + m]
                        : wi[((size_t)b * 256 + (k - 256)) * 16 + m];
    g_Aw[e] = v;
}

// W2T[s][l][k] = W2[s][k][l]  (tiled transpose)
__global__ void kTw2(const float* __restrict__ W2) {
    __shared__ float t[32][33];
    int s  = blockIdx.z;
    int k0 = blockIdx.x * 32, l0 = blockIdx.y * 32;
    int tx = threadIdx.x, ty = threadIdx.y;       // 32 x 8
    #pragma unroll
    for (int i = 0; i < 32; i += 8)
        t[ty + i][tx] = W2[((size_t)s * 1024 + k0 + ty + i) * 256 + l0 + tx];
    __syncthreads();
    #pragma unroll
    for (int i = 0; i < 32; i += 8)
        g_W2T[((size_t)s * 256 + l0 + ty + i) * 1024 + k0 + tx] = t[tx][ty + i];
}

// yp[s][m][h] = sum_l y_M[l,m] * Wy[s][l][h]
__global__ void kY(const float* __restrict__ yM, const float* __restrict__ W1,
                   const float* __restrict__ V1) {
    __shared__ float sy[256 * 16];
    int s = blockIdx.x;
    int h = blockIdx.y * 128 + threadIdx.x;
    #pragma unroll
    for (int i = 0; i < 32; i++) sy[threadIdx.x + 128 * i] = yM[threadIdx.x + 128 * i];
    __syncthreads();
    const float* base = (s < NSTEP)
        ? (W1 + ((size_t)s * 1280 + 1024) * 1024 + h)
        : (V1 + (size_t)1024 * 1024 + h);
    float acc[16];
    #pragma unroll
    for (int m = 0; m < 16; m++) acc[m] = 0.f;
    for (int l = 0; l < 256; l++) {
        float w = base[(size_t)l * 1024];
        #pragma unroll
        for (int m = 0; m < 16; m++) acc[m] += sy[l * 16 + m] * w;
    }
    #pragma unroll
    for (int m = 0; m < 16; m++) g_yp[((size_t)s * 16 + m) * HH + h] = acc[m];
}

// Big precompute GEMM: P[s][row][h] = Aw[row,:] @ Wcat[:, s*1024+h] + yp[s][m][h] + bias
__global__ __launch_bounds__(256) void kGemmP(const float* __restrict__ W1,
                                              const float* __restrict__ V1,
                                              const float* __restrict__ b1,
                                              const float* __restrict__ c1) {
    __shared__ float sA[2][8][132];
    __shared__ float sB[2][8][128];
    int tid = threadIdx.x;
    int n0 = blockIdx.x * 128;        // col tile (88)
    int r0 = blockIdx.y * 128;        // row tile (8)
    int s = n0 >> 10;
    int hbase = n0 & 1023;
    const float* Bbase = (s < NSTEP)
        ? (W1 + ((size_t)s * 1280 + 512) * 1024 + hbase)
        : (V1 + (size_t)512 * 1024 + hbase);

    int a_row = tid >> 1;
    int a_k   = (tid & 1) * 4;
    int b_k   = tid >> 5;
    int b_col = (tid & 31) * 4;
    int tx = tid & 15, ty = tid >> 4;

    const float* Aptr = g_Aw + (size_t)(r0 + a_row) * KW + a_k;
    const float* Bptr = Bbase + (size_t)b_k * 1024 + b_col;

    float acc[8][8];
    #pragma unroll
    for (int i = 0; i < 8; i++)
        #pragma unroll
        for (int j = 0; j < 8; j++) acc[i][j] = 0.f;

    float4 ga = *(const float4*)(Aptr);
    float4 gb = *(const float4*)(Bptr);
    sA[0][a_k + 0][a_row] = ga.x; sA[0][a_k + 1][a_row] = ga.y;
    sA[0][a_k + 2][a_row] = ga.z; sA[0][a_k + 3][a_row] = ga.w;
    *(float4*)&sB[0][b_k][b_col] = gb;
    __syncthreads();

    int buf = 0;
    for (int kt = 0; kt < 64; kt++) {
        float4 na, nb;
        if (kt < 63) {
            int kn = (kt + 1) * 8;
            na = *(const float4*)(Aptr + kn);
            nb = *(const float4*)(Bptr + (size_t)kn * 1024);
        }
        #pragma unroll
        for (int kk = 0; kk < 8; kk++) {
            float a[8], bv[8];
            *(float4*)&a[0]  = *(const float4*)&sA[buf][kk][ty * 8];
            *(float4*)&a[4]  = *(const float4*)&sA[buf][kk][ty * 8 + 4];
            *(float4*)&bv[0] = *(const float4*)&sB[buf][kk][tx * 8];
            *(float4*)&bv[4] = *(const float4*)&sB[buf][kk][tx * 8 + 4];
            #pragma unroll
            for (int i = 0; i < 8; i++)
                #pragma unroll
                for (int j = 0; j < 8; j++) acc[i][j] += a[i] * bv[j];
        }
        if (kt < 63) {
            int nbf = buf ^ 1;
            sA[nbf][a_k + 0][a_row] = na.x; sA[nbf][a_k + 1][a_row] = na.y;
            sA[nbf][a_k + 2][a_row] = na.z; sA[nbf][a_k + 3][a_row] = na.w;
            *(float4*)&sB[nbf][b_k][b_col] = nb;
            __syncthreads();
            buf = nbf;
        }
    }

    const float* bias = (s < NSTEP) ? (b1 + s * 1024) : c1;
    #pragma unroll
    for (int i = 0; i < 8; i++) {
        int row = r0 + ty * 8 + i;
        int m = row & 15;
        float* dst        = g_P  + (size_t)s * P_STRIDE + (size_t)row * HH + hbase + tx * 8;
        const float* ypp  = g_yp + ((size_t)s * 16 + m) * HH + hbase + tx * 8;
        const float* bp   = bias + hbase + tx * 8;
        #pragma unroll
        for (int j = 0; j < 8; j++) dst[j] = acc[i][j] + ypp[j] + bp[j];
    }
}

// ============ sequential per-step kernels ============

// init: copy phi, emit s_stack slot 0
__global__ void kA0(const float* __restrict__ phi_in, float* __restrict__ out,
                    int inter, int reOff, int imOff) {
    int b = blockIdx.x, l = threadIdx.x;
    float p = phi_in[b * LS + l];
    g_phi[b * LS + l] = p;
    float sv, cv; sincosf(p, &sv, &cv);
    write_s(out, (b * (NSTEP + 1)) * LS + l, cv, sv, inter, reOff, imOff);
}

// spart[b][j] = [cos(phi_b)|sin(phi_b)] @ (W1[s] rows 0:512 | V1 rows 0:512)
__global__ __launch_bounds__(256) void kB(const float* __restrict__ W1,
                                          const float* __restrict__ V1, int step) {
    __shared__ float sc[4][512];
    int tid = threadIdx.x;
    int j0 = blockIdx.x * 256, b0 = blockIdx.y * 4;
    #pragma unroll
    for (int i = 0; i < 4; i++) {
        int lin = tid + 256 * i; int bi = lin >> 8, l = lin & 255;
        float sv, cv; sincosf(g_phi[(b0 + bi) * LS + l], &sv, &cv);
        sc[bi][l] = cv; sc[bi][256 + l] = sv;
    }
    __syncthreads();
    int hg = tid & 63, bl = tid >> 6;
    int j = j0 + hg * 4;
    const float* base = (j < 1024) ? (W1 + (size_t)step * 1280 * 1024 + j)
                                   : (V1 + (j - 1024));
    float ax = 0.f, ay = 0.f, az = 0.f, aw = 0.f;
    #pragma unroll 2
    for (int k = 0; k < 512; k += 4) {
        float4 cs = *(const float4*)&sc[bl][k];
        float4 w;
        w = *(const float4*)(base + (size_t)k * 1024);
        ax += cs.x * w.x; ay += cs.x * w.y; az += cs.x * w.z; aw += cs.x * w.w;
        w = *(const float4*)(base + (size_t)(k + 1) * 1024);
        ax += cs.y * w.x; ay += cs.y * w.y; az += cs.y * w.z; aw += cs.y * w.w;
        w = *(const float4*)(base + (size_t)(k + 2) * 1024);
        ax += cs.z * w.x; ay += cs.z * w.y; az += cs.z * w.z; aw += cs.z * w.w;
        w = *(const float4*)(base + (size_t)(k + 3) * 1024);
        ax += cs.w * w.x; ay += cs.w * w.y; az += cs.w * w.z; aw += cs.w * w.w;
    }
    float4 r; r.x = ax; r.y = ay; r.z = az; r.w = aw;
    *(float4*)&g_spart[(b0 + bl) * 2048 + j] = r;
}

// rho + g accumulation. grid 64 (per b), 256 threads, 4 h per thread (stride 256).
__global__ __launch_bounds__(256) void kC(const float* __restrict__ V2,
                                          const float* __restrict__ c2,
                                          float* __restrict__ out, int step,
                                          int rhoOff, int rhoStride) {
    int b = blockIdx.x, tid = threadIdx.x;
    const float* sp = g_spart + b * 2048;
    float sp1[4], spv[4], v2r[4], gacc[4];
    int h[4];
    #pragma unroll
    for (int j = 0; j < 4; j++) {
        h[j] = tid + 256 * j;
        sp1[j] = sp[h[j]]; spv[j] = sp[1024 + h[j]];
        v2r[j] = V2[h[j]]; gacc[j] = 0.f;
    }
    const float* Pv = g_P + (size_t)NSTEP * P_STRIDE + (size_t)(b * 16) * HH;
    const float* Ps = g_P + (size_t)step  * P_STRIDE + (size_t)(b * 16) * HH;
    __shared__ float swarp[8];
    __shared__ float srho;
    float c2v = c2[0];
    float rhosum = 0.f;

    float pv_r[4], ps_r[4];
    #pragma unroll
    for (int j = 0; j < 4; j++) { pv_r[j] = Pv[h[j]]; ps_r[j] = Ps[h[j]]; }

    for (int m = 0; m < 16; m++) {
        float part = 0.f, hh_r[4];
        #pragma unroll
        for (int j = 0; j < 4; j++) {
            float hv = spv[j] + pv_r[j]; hv = hv > 0.f ? hv : 0.f;
            part += hv * v2r[j];
            float hx = sp1[j] + ps_r[j]; hh_r[j] = hx > 0.f ? hx : 0.f;
        }
        float pv_n[4] = {0.f,0.f,0.f,0.f}, ps_n[4] = {0.f,0.f,0.f,0.f};
        if (m < 15) {
            const float* pv = Pv + (size_t)(m + 1) * HH;
            const float* ps = Ps + (size_t)(m + 1) * HH;
            #pragma unroll
            for (int j = 0; j < 4; j++) { pv_n[j] = pv[h[j]]; ps_n[j] = ps[h[j]]; }
        }
        #pragma unroll
        for (int off = 16; off > 0; off >>= 1)
            part += __shfl_xor_sync(0xffffffffu, part, off);
        if ((tid & 31) == 0) swarp[tid >> 5] = part;
        __syncthreads();
        if (tid == 0) {
            float t = 0.f;
            #pragma unroll
            for (int w = 0; w < 8; w++) t += swarp[w];
            float rho = 1.f / (1.f + expf(-(t + c2v)));
            srho = rho;
            int ridx = (b * NSTEP + step) * MM + m;
            out[rhoOff + ridx * rhoStride] = rho;
            if (rhoStride == 2) out[rhoOff + ridx * 2 + 1] = 0.f;
        }
        __syncthreads();
        float rho = srho;
        rhosum += rho;
        #pragma unroll
        for (int j = 0; j < 4; j++) gacc[j] += rho * hh_r[j];
        #pragma unroll
        for (int j = 0; j < 4; j++) { pv_r[j] = pv_n[j]; ps_r[j] = ps_n[j]; }
    }
    #pragma unroll
    for (int j = 0; j < 4; j++) g_g[b * HH + h[j]] = gacc[j];
    if (tid == 0) g_rhosum[b] = rhosum;
}

// eta GEMM + phi update + s_stack slot step+1. grid (8,16), 128 threads.
__global__ __launch_bounds__(128) void kD(const float* __restrict__ b2,
                                          float* __restrict__ out, int step,
                                          int inter, int reOff, int imOff) {
    __shared__ float sg[4][1024];
    int l  = blockIdx.x * 32 + (threadIdx.x & 31);
    int bl = threadIdx.x >> 5;
    int b  = blockIdx.y * 4 + bl;
    const float4* gg = (const float4*)(g_g + (size_t)blockIdx.y * 4 * 1024);
    float4* sg4 = (float4*)sg;
    #pragma unroll
    for (int i = 0; i < 8; i++) sg4[threadIdx.x + 128 * i] = gg[threadIdx.x + 128 * i];
    __syncthreads();
    const float* w = g_W2T + ((size_t)step * 256 + l) * 1024;
    float acc = 0.f;
    #pragma unroll 8
    for (int k = 0; k < 1024; k += 4) {
        float4 wv = *(const float4*)(w + k);
        float4 gv = *(const float4*)(&sg[bl][k]);
        acc += wv.x * gv.x + wv.y * gv.y + wv.z * gv.z + wv.w * gv.w;
    }
    float eta = acc + g_rhosum[b] * b2[step * 256 + l];
    float phin = g_phi[b * LS + l] - eta;
    g_phi[b * LS + l] = phin;
    float sv, cv; sincosf(phin, &sv, &cv);
    write_s(out, (b * (NSTEP + 1) + step + 1) * LS + l, cv, sv, inter, reOff, imOff);
}

// ============ launch ============
extern "C" void kernel_launch(void* const* d_in, const int* in_sizes, int n_in,
                              void* d_out, int out_size) {
    // Input resolution (phi has unique size 16384; verify dict order, else size-scan)
    const float *phi=0,*wr=0,*wi=0,*yM=0,*W1=0,*b1=0,*W2=0,*b2=0,*V1=0,*c1=0,*V2=0,*c2=0;
    if (n_in == 12 && in_sizes[0] == 16384) {
        phi=(const float*)d_in[0]; wr=(const float*)d_in[1]; wi=(const float*)d_in[2];
        yM=(const float*)d_in[3];  W1=(const float*)d_in[4]; b1=(const float*)d_in[5];
        W2=(const float*)d_in[6];  b2=(const float*)d_in[7]; V1=(const float*)d_in[8];
        c1=(const float*)d_in[9];  V2=(const float*)d_in[10];c2=(const float*)d_in[11];
    } else {
        int seen262144 = 0, seen1024 = 0;
        for (int i = 0; i < n_in; i++) {
            const float* p = (const float*)d_in[i];
            switch (in_sizes[i]) {
                case 16384:    phi = p; break;
                case 4096:     yM  = p; break;
                case 13107200: W1  = p; break;
                case 10240:    b1  = p; break;
                case 2621440:  W2  = p; break;
                case 2560:     b2  = p; break;
                case 1310720:  V1  = p; break;
                case 1:        c2  = p; break;
                case 262144:   if (seen262144++ == 0) wr = p; else wi = p; break;
                case 1024:     if (seen1024++   == 0) c1 = p; else V2 = p; break;
                default: break;
            }
        }
    }
    float* out = (float*)d_out;

    // Output layout by out_size:
    //  370688 (default): PLANAR  [Re(s) 180224 | Im(s) 180224 | rho 10240]
    //  190464          : REAL    [Re(s) 180224 | rho 10240]   (complex->float cast)
    //  380928          : INTER   [s interleaved 360448 | (rho,0) pairs 20480]
    int inter = 0, reOff = 0, imOff = N_SELEM, rhoOff = 2 * N_SELEM, rhoStride = 1;
    if (out_size == 190464) { imOff = -1; rhoOff = N_SELEM; }
    else if (out_size == 380928) { inter = 1; rhoOff = 2 * N_SELEM; rhoStride = 2; }

    // phi-independent precompute
    kTw  <<<2048, 256>>>(wr, wi);
    kTw2 <<<dim3(32, 8, 10), dim3(32, 8)>>>(W2);
    kY   <<<dim3(11, 8), 128>>>(yM, W1, V1);
    kGemmP<<<dim3(88, 8), 256>>>(W1, V1, b1, c1);

    // sequential chain
    kA0<<<64, 256>>>(phi, out, inter, reOff, imOff);
    for (int s = 0; s < NSTEP; s++) {
        kB<<<dim3(8, 16), 256>>>(W1, V1, s);
        kC<<<64, 256>>>(V2, c2, out, s, rhoOff, rhoStride);
        kD<<<dim3(8, 16), 128>>>(b2, out, s, inter, reOff, imOff);
    }
}

// round 5
// speedup vs baseline: 1.2165x; 1.2165x over previous
#include <cuda_runtime.h>
#include <math.h>

// Problem constants
#define B      64
#define LS     256
#define MM     16
#define NSTEP  10
#define HH     1024
#define BM     1024           // B*MM rows
#define KW     512            // w_r|w_i contraction dim
#define NSEG   11             // 10 W1 steps + 1 V1
#define P_STRIDE (BM*HH)      // 1048576

#define N_SELEM (B*(NSTEP+1)*LS)     // 180224 complex elements

// ---- scratch (static __device__, allocation-free) ----
__device__ float g_P[NSEG * BM * HH];        // precomputed (w,y,bias) pre-activations
__device__ float g_Aw[BM * KW];              // transposed w: [row=b*16+m][k]
__device__ float g_W2T[NSTEP * LS * HH];     // W2 transposed: [s][l][k]
__device__ float g_yp[NSEG * MM * HH];       // y-part per (s,m,h)
__device__ float g_phi[B * LS];
__device__ float g_S[2 * LS * B];            // [k][b]: k<256 cos, k>=256 sin  (128KB)
__device__ float g_spart[B * 2048];          // [b][j]: j<1024 W1-path, else V1-path
__device__ float g_gT[HH * B];               // [k][b] = sum_m rho*h  (transposed)
__device__ float g_rhosum[B];

// Generic s-writer: idx = (b*(NSTEP+1)+t)*LS + l
__device__ __forceinline__ void write_s(float* out, int idx, float cv, float sv,
                                        int inter, int imOff) {
    if (inter) {
        out[2 * idx] = cv; out[2 * idx + 1] = sv;
    } else {
        out[idx] = cv;
        if (imOff >= 0) out[imOff + idx] = sv;
    }
}

// ============ precompute kernels (parallel, phi-independent) ============

// Aw[row=b*16+m][k] = k<256 ? w_r[b,k,m] : w_i[b,k-256,m]
__global__ void kTw(const float* __restrict__ wr, const float* __restrict__ wi) {
    int e = blockIdx.x * 256 + threadIdx.x;       // 524288 elements
    int row = e >> 9, k = e & 511;
    int b = row >> 4, m = row & 15;
    float v = (k < 256) ? wr[((size_t)b * 256 + k) * 16 + m]
                        : wi[((size_t)b * 256 + (k - 256)) * 16 + m];
    g_Aw[e] = v;
}

// W2T[s][l][k] = W2[s][k][l]  (tiled transpose)
__global__ void kTw2(const float* __restrict__ W2) {
    __shared__ float t[32][33];
    int s  = blockIdx.z;
    int k0 = blockIdx.x * 32, l0 = blockIdx.y * 32;
    int tx = threadIdx.x, ty = threadIdx.y;       // 32 x 8
    #pragma unroll
    for (int i = 0; i < 32; i += 8)
        t[ty + i][tx] = W2[((size_t)s * 1024 + k0 + ty + i) * 256 + l0 + tx];
    __syncthreads();
    #pragma unroll
    for (int i = 0; i < 32; i += 8)
        g_W2T[((size_t)s * 256 + l0 + ty + i) * 1024 + k0 + tx] = t[tx][ty + i];
}

// yp[s][m][h] = sum_l y_M[l,m] * Wy[s][l][h]
__global__ void kY(const float* __restrict__ yM, const float* __restrict__ W1,
                   const float* __restrict__ V1) {
    __shared__ float sy[256 * 16];
    int s = blockIdx.x;
    int h = blockIdx.y * 128 + threadIdx.x;
    #pragma unroll
    for (int i = 0; i < 32; i++) sy[threadIdx.x + 128 * i] = yM[threadIdx.x + 128 * i];
    __syncthreads();
    const float* base = (s < NSTEP)
        ? (W1 + ((size_t)s * 1280 + 1024) * 1024 + h)
        : (V1 + (size_t)1024 * 1024 + h);
    float acc[16];
    #pragma unroll
    for (int m = 0; m < 16; m++) acc[m] = 0.f;
    for (int l = 0; l < 256; l++) {
        float w = base[(size_t)l * 1024];
        #pragma unroll
        for (int m = 0; m < 16; m++) acc[m] += sy[l * 16 + m] * w;
    }
    #pragma unroll
    for (int m = 0; m < 16; m++) g_yp[((size_t)s * 16 + m) * HH + h] = acc[m];
}

// Big precompute GEMM: P[s][row][h] = Aw[row,:] @ Wcat[:, s*1024+h] + yp[s][m][h] + bias
__global__ __launch_bounds__(256) void kGemmP(const float* __restrict__ W1,
                                              const float* __restrict__ V1,
                                              const float* __restrict__ b1,
                                              const float* __restrict__ c1) {
    __shared__ float sA[2][8][132];
    __shared__ float sB[2][8][128];
    int tid = threadIdx.x;
    int n0 = blockIdx.x * 128;        // col tile (88)
    int r0 = blockIdx.y * 128;        // row tile (8)
    int s = n0 >> 10;
    int hbase = n0 & 1023;
    const float* Bbase = (s < NSTEP)
        ? (W1 + ((size_t)s * 1280 + 512) * 1024 + hbase)
        : (V1 + (size_t)512 * 1024 + hbase);

    int a_row = tid >> 1;
    int a_k   = (tid & 1) * 4;
    int b_k   = tid >> 5;
    int b_col = (tid & 31) * 4;
    int tx = tid & 15, ty = tid >> 4;

    const float* Aptr = g_Aw + (size_t)(r0 + a_row) * KW + a_k;
    const float* Bptr = Bbase + (size_t)b_k * 1024 + b_col;

    float acc[8][8];
    #pragma unroll
    for (int i = 0; i < 8; i++)
        #pragma unroll
        for (int j = 0; j < 8; j++) acc[i][j] = 0.f;

    float4 ga = *(const float4*)(Aptr);
    float4 gb = *(const float4*)(Bptr);
    sA[0][a_k + 0][a_row] = ga.x; sA[0][a_k + 1][a_row] = ga.y;
    sA[0][a_k + 2][a_row] = ga.z; sA[0][a_k + 3][a_row] = ga.w;
    *(float4*)&sB[0][b_k][b_col] = gb;
    __syncthreads();

    int buf = 0;
    for (int kt = 0; kt < 64; kt++) {
        float4 na, nb;
        if (kt < 63) {
            int kn = (kt + 1) * 8;
            na = *(const float4*)(Aptr + kn);
            nb = *(const float4*)(Bptr + (size_t)kn * 1024);
        }
        #pragma unroll
        for (int kk = 0; kk < 8; kk++) {
            float a[8], bv[8];
            *(float4*)&a[0]  = *(const float4*)&sA[buf][kk][ty * 8];
            *(float4*)&a[4]  = *(const float4*)&sA[buf][kk][ty * 8 + 4];
            *(float4*)&bv[0] = *(const float4*)&sB[buf][kk][tx * 8];
            *(float4*)&bv[4] = *(const float4*)&sB[buf][kk][tx * 8 + 4];
            #pragma unroll
            for (int i = 0; i < 8; i++)
                #pragma unroll
                for (int j = 0; j < 8; j++) acc[i][j] += a[i] * bv[j];
        }
        if (kt < 63) {
            int nbf = buf ^ 1;
            sA[nbf][a_k + 0][a_row] = na.x; sA[nbf][a_k + 1][a_row] = na.y;
            sA[nbf][a_k + 2][a_row] = na.z; sA[nbf][a_k + 3][a_row] = na.w;
            *(float4*)&sB[nbf][b_k][b_col] = nb;
            __syncthreads();
            buf = nbf;
        }
    }

    const float* bias = (s < NSTEP) ? (b1 + s * 1024) : c1;
    #pragma unroll
    for (int i = 0; i < 8; i++) {
        int row = r0 + ty * 8 + i;
        int m = row & 15;
        float* dst        = g_P  + (size_t)s * P_STRIDE + (size_t)row * HH + hbase + tx * 8;
        const float* ypp  = g_yp + ((size_t)s * 16 + m) * HH + hbase + tx * 8;
        const float* bp   = bias + hbase + tx * 8;
        #pragma unroll
        for (int j = 0; j < 8; j++) dst[j] = acc[i][j] + ypp[j] + bp[j];
    }
}

// ============ sequential per-step kernels ============

// init: copy phi, emit s_stack slot 0, seed g_S
__global__ void kA0(const float* __restrict__ phi_in, float* __restrict__ out,
                    int inter, int imOff) {
    int b = blockIdx.x, l = threadIdx.x;
    float p = phi_in[b * LS + l];
    g_phi[b * LS + l] = p;
    float sv, cv; sincosf(p, &sv, &cv);
    write_s(out, (b * (NSTEP + 1)) * LS + l, cv, sv, inter, imOff);
    g_S[l * B + b] = cv;
    g_S[(256 + l) * B + b] = sv;
}

// kB2: spart[b][j] = sum_k S[k][b] * W[k][j].  Weight read ONCE (amortized over all b).
// grid 128 (j-tile 16), 256 threads: jloc = t&15, bgroup = t>>4 (4 b's each).
__global__ __launch_bounds__(256) void kB2(const float* __restrict__ W1,
                                           const float* __restrict__ V1, int step) {
    __shared__ float sS[64 * 64];   // [k-chunk 64][b 64] = 16KB
    int tid = threadIdx.x;
    int j0 = blockIdx.x * 16;
    int jloc = tid & 15;
    int b0 = (tid >> 4) * 4;
    int j = j0 + jloc;
    const float* wp = (j0 < 1024) ? (W1 + (size_t)step * 1280 * 1024 + j)
                                  : (V1 + (j - 1024));
    float acc0 = 0.f, acc1 = 0.f, acc2 = 0.f, acc3 = 0.f;

    for (int kc = 0; kc < 8; kc++) {
        const float4* src = (const float4*)(g_S + kc * 64 * 64);
        float4* dst = (float4*)sS;
        #pragma unroll
        for (int r = 0; r < 4; r++) dst[tid + 256 * r] = src[tid + 256 * r];
        __syncthreads();
        const float* wk = wp + (size_t)(kc * 64) * 1024;
        #pragma unroll 8
        for (int kk = 0; kk < 64; kk++) {
            float w = wk[(size_t)kk * 1024];
            float4 sv = *(const float4*)&sS[kk * 64 + b0];
            acc0 += w * sv.x; acc1 += w * sv.y; acc2 += w * sv.z; acc3 += w * sv.w;
        }
        __syncthreads();
    }
    g_spart[(b0 + 0) * 2048 + j] = acc0;
    g_spart[(b0 + 1) * 2048 + j] = acc1;
    g_spart[(b0 + 2) * 2048 + j] = acc2;
    g_spart[(b0 + 3) * 2048 + j] = acc3;
}

// rho + g accumulation. grid 64 (per b), 256 threads, 4 h per thread (stride 256).
// Writes g transposed: g_gT[k][b].
__global__ __launch_bounds__(256) void kC(const float* __restrict__ V2,
                                          const float* __restrict__ c2,
                                          float* __restrict__ out, int step,
                                          int rhoOff, int rhoStride) {
    int b = blockIdx.x, tid = threadIdx.x;
    const float* sp = g_spart + b * 2048;
    float sp1[4], spv[4], v2r[4], gacc[4];
    int h[4];
    #pragma unroll
    for (int j = 0; j < 4; j++) {
        h[j] = tid + 256 * j;
        sp1[j] = sp[h[j]]; spv[j] = sp[1024 + h[j]];
        v2r[j] = V2[h[j]]; gacc[j] = 0.f;
    }
    const float* Pv = g_P + (size_t)NSTEP * P_STRIDE + (size_t)(b * 16) * HH;
    const float* Ps = g_P + (size_t)step  * P_STRIDE + (size_t)(b * 16) * HH;
    __shared__ float swarp[8];
    __shared__ float srho;
    float c2v = c2[0];
    float rhosum = 0.f;

    float pv_r[4], ps_r[4];
    #pragma unroll
    for (int j = 0; j < 4; j++) { pv_r[j] = Pv[h[j]]; ps_r[j] = Ps[h[j]]; }

    for (int m = 0; m < 16; m++) {
        float part = 0.f, hh_r[4];
        #pragma unroll
        for (int j = 0; j < 4; j++) {
            float hv = spv[j] + pv_r[j]; hv = hv > 0.f ? hv : 0.f;
            part += hv * v2r[j];
            float hx = sp1[j] + ps_r[j]; hh_r[j] = hx > 0.f ? hx : 0.f;
        }
        float pv_n[4] = {0.f,0.f,0.f,0.f}, ps_n[4] = {0.f,0.f,0.f,0.f};
        if (m < 15) {
            const float* pv = Pv + (size_t)(m + 1) * HH;
            const float* ps = Ps + (size_t)(m + 1) * HH;
            #pragma unroll
            for (int j = 0; j < 4; j++) { pv_n[j] = pv[h[j]]; ps_n[j] = ps[h[j]]; }
        }
        #pragma unroll
        for (int off = 16; off > 0; off >>= 1)
            part += __shfl_xor_sync(0xffffffffu, part, off);
        if ((tid & 31) == 0) swarp[tid >> 5] = part;
        __syncthreads();
        if (tid == 0) {
            float t = 0.f;
            #pragma unroll
            for (int w = 0; w < 8; w++) t += swarp[w];
            float rho = 1.f / (1.f + expf(-(t + c2v)));
            srho = rho;
            int ridx = (b * NSTEP + step) * MM + m;
            out[rhoOff + ridx * rhoStride] = rho;
            if (rhoStride == 2) out[rhoOff + ridx * 2 + 1] = 0.f;
        }
        __syncthreads();
        float rho = srho;
        rhosum += rho;
        #pragma unroll
        for (int j = 0; j < 4; j++) gacc[j] += rho * hh_r[j];
        #pragma unroll
        for (int j = 0; j < 4; j++) { pv_r[j] = pv_n[j]; ps_r[j] = ps_n[j]; }
    }
    #pragma unroll
    for (int j = 0; j < 4; j++) g_gT[h[j] * B + b] = gacc[j];
    if (tid == 0) g_rhosum[b] = rhosum;
}

// kD2: eta[b][l] = g[b,:]@W2T[s][l,:] + rhosum[b]*b2[s][l]; phi update; emit s; seed g_S.
// grid 32 (l-tile 8), 256 threads: lloc = t>>5, b-pair = 2*(t&31).
__global__ __launch_bounds__(256) void kD2(const float* __restrict__ b2,
                                           float* __restrict__ out, int step,
                                           int inter, int imOff) {
    __shared__ float sW[8 * 1024];   // 32KB: 8 W2T rows
    int tid = threadIdx.x;
    int l0 = blockIdx.x * 8;
    int lloc = tid >> 5;
    int l = l0 + lloc;
    int b0 = (tid & 31) * 2;

    const float4* src = (const float4*)(g_W2T + ((size_t)step * 256 + l0) * 1024);
    float4* dst = (float4*)sW;
    #pragma unroll
    for (int r = 0; r < 8; r++) dst[tid + 256 * r] = src[tid + 256 * r];
    __syncthreads();

    float acc0 = 0.f, acc1 = 0.f;
    const float* wrow = sW + lloc * 1024;
    const float2* gp = (const float2*)(g_gT + b0);
    #pragma unroll 8
    for (int k = 0; k < 1024; k++) {
        float w = wrow[k];
        float2 gv = gp[k * 32];   // g_gT[k*64 + b0]
        acc0 += w * gv.x; acc1 += w * gv.y;
    }

    float b2v = b2[step * 256 + l];
    #pragma unroll
    for (int i = 0; i < 2; i++) {
        int b = b0 + i;
        float eta = (i == 0 ? acc0 : acc1) + g_rhosum[b] * b2v;
        float phin = g_phi[b * LS + l] - eta;
        g_phi[b * LS + l] = phin;
        float sv, cv; sincosf(phin, &sv, &cv);
        write_s(out, (b * (NSTEP + 1) + step + 1) * LS + l, cv, sv, inter, imOff);
        g_S[l * B + b] = cv;
        g_S[(256 + l) * B + b] = sv;
    }
}

// ============ launch ============
extern "C" void kernel_launch(void* const* d_in, const int* in_sizes, int n_in,
                              void* d_out, int out_size) {
    const float *phi=0,*wr=0,*wi=0,*yM=0,*W1=0,*b1=0,*W2=0,*b2=0,*V1=0,*c1=0,*V2=0,*c2=0;
    if (n_in == 12 && in_sizes[0] == 16384) {
        phi=(const float*)d_in[0]; wr=(const float*)d_in[1]; wi=(const float*)d_in[2];
        yM=(const float*)d_in[3];  W1=(const float*)d_in[4]; b1=(const float*)d_in[5];
        W2=(const float*)d_in[6];  b2=(const float*)d_in[7]; V1=(const float*)d_in[8];
        c1=(const float*)d_in[9];  V2=(const float*)d_in[10];c2=(const float*)d_in[11];
    } else {
        int seen262144 = 0, seen1024 = 0;
        for (int i = 0; i < n_in; i++) {
            const float* p = (const float*)d_in[i];
            switch (in_sizes[i]) {
                case 16384:    phi = p; break;
                case 4096:     yM  = p; break;
                case 13107200: W1  = p; break;
                case 10240:    b1  = p; break;
                case 2621440:  W2  = p; break;
                case 2560:     b2  = p; break;
                case 1310720:  V1  = p; break;
                case 1:        c2  = p; break;
                case 262144:   if (seen262144++ == 0) wr = p; else wi = p; break;
                case 1024:     if (seen1024++   == 0) c1 = p; else V2 = p; break;
                default: break;
            }
        }
    }
    float* out = (float*)d_out;

    // Output layout by out_size (round-3 pass came through the 190464 branch):
    //  190464: REAL   [Re(s) 180224 | rho 10240]           (complex->float32 cast)
    //  370688: PLANAR [Re 180224 | Im 180224 | rho 10240]
    //  380928: INTER  [s interleaved 360448 | (rho,0) pairs]
    int inter = 0, imOff = -1, rhoOff = N_SELEM, rhoStride = 1;
    if (out_size == 370688)      { imOff = N_SELEM; rhoOff = 2 * N_SELEM; }
    else if (out_size == 380928) { inter = 1; imOff = -1; rhoOff = 2 * N_SELEM; rhoStride = 2; }

    // phi-independent precompute
    kTw  <<<2048, 256>>>(wr, wi);
    kTw2 <<<dim3(32, 8, 10), dim3(32, 8)>>>(W2);
    kY   <<<dim3(11, 8), 128>>>(yM, W1, V1);
    kGemmP<<<dim3(88, 8), 256>>>(W1, V1, b1, c1);

    // sequential chain (3 kernels/step; sincos for next step fused into kD2)
    kA0<<<64, 256>>>(phi, out, inter, imOff);
    for (int s = 0; s < NSTEP; s++) {
        kB2<<<128, 256>>>(W1, V1, s);
        kC <<<64, 256>>>(V2, c2, out, s, rhoOff, rhoStride);
        kD2<<<32, 256>>>(b2, out, s, inter, imOff);
    }
}

// round 6
// speedup vs baseline: 1.2258x; 1.0077x over previous
#include <cuda_runtime.h>
#include <math.h>

// Problem constants
#define B      64
#define LS     256
#define MM     16
#define NSTEP  10
#define HH     1024
#define BM     1024
#define KW     512
#define NSEG   11
#define P_STRIDE (BM*HH)

#define N_SELEM (B*(NSTEP+1)*LS)     // 180224

#define NB_CHAIN 128                 // chain grid (<=148 SMs -> co-resident)

// ---- scratch (static __device__, allocation-free) ----
__device__ float g_P[NSEG * BM * HH];
__device__ float g_Aw[BM * KW];
__device__ float g_W2T[NSTEP * LS * HH];
__device__ float g_yp[NSEG * MM * HH];
__device__ float g_phi[B * LS];
__device__ float g_S[2 * LS * B];            // [k][b]
__device__ float g_spart[B * 2048];          // [b][j]
__device__ float g_gT[HH * B];               // [k][b]
__device__ float g_rhosum[B];

// grid-barrier state (reset each replay by kReset)
__device__ int g_bar_count;
__device__ int g_bar_release;

__global__ void kReset() { g_bar_count = 0; g_bar_release = 0; }

__device__ __forceinline__ void grid_bar(int* sepoch) {
    __syncthreads();
    if (threadIdx.x == 0) {
        int e = ++(*sepoch);
        __threadfence();
        int a = atomicAdd(&g_bar_count, 1) + 1;
        if ((a & (NB_CHAIN - 1)) == 0) {
            atomicAdd(&g_bar_release, 1);
        } else {
            while (*(volatile int*)&g_bar_release < e) { __nanosleep(64); }
        }
        __threadfence();
    }
    __syncthreads();
}

__device__ __forceinline__ void write_s(float* out, int idx, float cv, float sv,
                                        int inter, int imOff) {
    if (inter) {
        out[2 * idx] = cv; out[2 * idx + 1] = sv;
    } else {
        out[idx] = cv;
        if (imOff >= 0) out[imOff + idx] = sv;
    }
}

// ============ precompute kernels ============

__global__ void kTw(const float* __restrict__ wr, const float* __restrict__ wi) {
    int e = blockIdx.x * 256 + threadIdx.x;
    int row = e >> 9, k = e & 511;
    int b = row >> 4, m = row & 15;
    float v = (k < 256) ? wr[((size_t)b * 256 + k) * 16 + m]
                        : wi[((size_t)b * 256 + (k - 256)) * 16 + m];
    g_Aw[e] = v;
}

__global__ void kTw2(const float* __restrict__ W2) {
    __shared__ float t[32][33];
    int s  = blockIdx.z;
    int k0 = blockIdx.x * 32, l0 = blockIdx.y * 32;
    int tx = threadIdx.x, ty = threadIdx.y;
    #pragma unroll
    for (int i = 0; i < 32; i += 8)
        t[ty + i][tx] = W2[((size_t)s * 1024 + k0 + ty + i) * 256 + l0 + tx];
    __syncthreads();
    #pragma unroll
    for (int i = 0; i < 32; i += 8)
        g_W2T[((size_t)s * 256 + l0 + ty + i) * 1024 + k0 + tx] = t[tx][ty + i];
}

__global__ void kY(const float* __restrict__ yM, const float* __restrict__ W1,
                   const float* __restrict__ V1) {
    __shared__ float sy[256 * 16];
    int s = blockIdx.x;
    int h = blockIdx.y * 128 + threadIdx.x;
    #pragma unroll
    for (int i = 0; i < 32; i++) sy[threadIdx.x + 128 * i] = yM[threadIdx.x + 128 * i];
    __syncthreads();
    const float* base = (s < NSTEP)
        ? (W1 + ((size_t)s * 1280 + 1024) * 1024 + h)
        : (V1 + (size_t)1024 * 1024 + h);
    float acc[16];
    #pragma unroll
    for (int m = 0; m < 16; m++) acc[m] = 0.f;
    #pragma unroll 4
    for (int l = 0; l < 256; l++) {
        float w = base[(size_t)l * 1024];
        #pragma unroll
        for (int m = 0; m < 16; m++) acc[m] += sy[l * 16 + m] * w;
    }
    #pragma unroll
    for (int m = 0; m < 16; m++) g_yp[((size_t)s * 16 + m) * HH + h] = acc[m];
}

// Big precompute GEMM (fp32, ~86% of FFMA roofline — tensor-core port is next)
__global__ __launch_bounds__(256) void kGemmP(const float* __restrict__ W1,
                                              const float* __restrict__ V1,
                                              const float* __restrict__ b1,
                                              const float* __restrict__ c1) {
    __shared__ float sA[2][8][132];
    __shared__ float sB[2][8][128];
    int tid = threadIdx.x;
    int n0 = blockIdx.x * 128;
    int r0 = blockIdx.y * 128;
    int s = n0 >> 10;
    int hbase = n0 & 1023;
    const float* Bbase = (s < NSTEP)
        ? (W1 + ((size_t)s * 1280 + 512) * 1024 + hbase)
        : (V1 + (size_t)512 * 1024 + hbase);

    int a_row = tid >> 1;
    int a_k   = (tid & 1) * 4;
    int b_k   = tid >> 5;
    int b_col = (tid & 31) * 4;
    int tx = tid & 15, ty = tid >> 4;

    const float* Aptr = g_Aw + (size_t)(r0 + a_row) * KW + a_k;
    const float* Bptr = Bbase + (size_t)b_k * 1024 + b_col;

    float acc[8][8];
    #pragma unroll
    for (int i = 0; i < 8; i++)
        #pragma unroll
        for (int j = 0; j < 8; j++) acc[i][j] = 0.f;

    float4 ga = *(const float4*)(Aptr);
    float4 gb = *(const float4*)(Bptr);
    sA[0][a_k + 0][a_row] = ga.x; sA[0][a_k + 1][a_row] = ga.y;
    sA[0][a_k + 2][a_row] = ga.z; sA[0][a_k + 3][a_row] = ga.w;
    *(float4*)&sB[0][b_k][b_col] = gb;
    __syncthreads();

    int buf = 0;
    for (int kt = 0; kt < 64; kt++) {
        float4 na, nb;
        if (kt < 63) {
            int kn = (kt + 1) * 8;
            na = *(const float4*)(Aptr + kn);
            nb = *(const float4*)(Bptr + (size_t)kn * 1024);
        }
        #pragma unroll
        for (int kk = 0; kk < 8; kk++) {
            float a[8], bv[8];
            *(float4*)&a[0]  = *(const float4*)&sA[buf][kk][ty * 8];
            *(float4*)&a[4]  = *(const float4*)&sA[buf][kk][ty * 8 + 4];
            *(float4*)&bv[0] = *(const float4*)&sB[buf][kk][tx * 8];
            *(float4*)&bv[4] = *(const float4*)&sB[buf][kk][tx * 8 + 4];
            #pragma unroll
            for (int i = 0; i < 8; i++)
                #pragma unroll
                for (int j = 0; j < 8; j++) acc[i][j] += a[i] * bv[j];
        }
        if (kt < 63) {
            int nbf = buf ^ 1;
            sA[nbf][a_k + 0][a_row] = na.x; sA[nbf][a_k + 1][a_row] = na.y;
            sA[nbf][a_k + 2][a_row] = na.z; sA[nbf][a_k + 3][a_row] = na.w;
            *(float4*)&sB[nbf][b_k][b_col] = nb;
            __syncthreads();
            buf = nbf;
        }
    }

    const float* bias = (s < NSTEP) ? (b1 + s * 1024) : c1;
    #pragma unroll
    for (int i = 0; i < 8; i++) {
        int row = r0 + ty * 8 + i;
        int m = row & 15;
        float* dst        = g_P  + (size_t)s * P_STRIDE + (size_t)row * HH + hbase + tx * 8;
        const float* ypp  = g_yp + ((size_t)s * 16 + m) * HH + hbase + tx * 8;
        const float* bp   = bias + hbase + tx * 8;
        #pragma unroll
        for (int j = 0; j < 8; j++) dst[j] = acc[i][j] + ypp[j] + bp[j];
    }
}

// ============ fused sequential chain (ONE kernel, grid barriers) ============
__global__ __launch_bounds__(256) void kChain(
    const float* __restrict__ phi_in, const float* __restrict__ b2,
    const float* __restrict__ V2, const float* __restrict__ c2,
    const float* __restrict__ W1, const float* __restrict__ V1,
    float* __restrict__ out, int inter, int imOff, int rhoOff, int rhoStride)
{
    __shared__ float shm[4096];      // 16KB workspace (phase-dependent)
    __shared__ float shv2[1024];
    __shared__ float shpart[16];
    __shared__ float shrho[16];
    __shared__ int sepoch;

    int tid = threadIdx.x, bid = blockIdx.x;
    if (tid == 0) sepoch = 0;
    #pragma unroll
    for (int i = 0; i < 4; i++) shv2[tid + 256 * i] = V2[tid + 256 * i];
    float c2v = c2[0];

    // ---- phase A0: init phi, s slot 0, g_S ----
    if (bid < 64) {
        int b = bid, l = tid;
        float p = phi_in[b * 256 + l];
        g_phi[b * 256 + l] = p;
        float sv, cv; sincosf(p, &sv, &cv);
        write_s(out, (b * 11) * 256 + l, cv, sv, inter, imOff);
        g_S[l * 64 + b] = cv;
        g_S[(256 + l) * 64 + b] = sv;
    }
    grid_bar(&sepoch);

    for (int step = 0; step < NSTEP; step++) {
        // ---- phase B: spart[b][j] = sum_k S[k][b] * W[k][j], j-tile 16/block ----
        {
            int j0 = bid * 16;
            int jloc = tid & 15, b0 = (tid >> 4) * 4;
            int j = j0 + jloc;
            const float* wp = (j0 < 1024) ? (W1 + (size_t)step * 1280 * 1024 + j)
                                          : (V1 + (j - 1024));
            float a0 = 0.f, a1 = 0.f, a2 = 0.f, a3 = 0.f;
            for (int kc = 0; kc < 8; kc++) {
                const float4* src = (const float4*)(g_S + kc * 4096);
                #pragma unroll
                for (int r = 0; r < 4; r++)
                    ((float4*)shm)[tid + 256 * r] = src[tid + 256 * r];
                __syncthreads();
                const float* wk = wp + (size_t)(kc * 64) * 1024;
                #pragma unroll 8
                for (int kk = 0; kk < 64; kk++) {
                    float w = wk[(size_t)kk * 1024];
                    float4 s4 = *(const float4*)&shm[kk * 64 + b0];
                    a0 += w * s4.x; a1 += w * s4.y; a2 += w * s4.z; a3 += w * s4.w;
                }
                __syncthreads();
            }
            g_spart[(b0 + 0) * 2048 + j] = a0;
            g_spart[(b0 + 1) * 2048 + j] = a1;
            g_spart[(b0 + 2) * 2048 + j] = a2;
            g_spart[(b0 + 3) * 2048 + j] = a3;
        }
        grid_bar(&sepoch);

        // ---- phase C: rho (warp per 2 m, no block barriers in m) + g ----
        if (bid < 64) {
            int b = bid;
            const float4* sp4 = (const float4*)(g_spart + b * 2048);
            #pragma unroll
            for (int r = 0; r < 2; r++)
                ((float4*)shm)[tid + 256 * r] = sp4[tid + 256 * r];
            __syncthreads();
            int w = tid >> 5, lane = tid & 31;
            const float* Pv = g_P + (size_t)NSTEP * P_STRIDE + (size_t)(b * 16) * HH;
            const float* rowA = Pv + (size_t)w * 1024;
            const float* rowB = Pv + (size_t)(w + 8) * 1024;
            float partA = 0.f, partB = 0.f;
            #pragma unroll 8
            for (int i = 0; i < 32; i++) {
                int h = lane + 32 * i;
                float spv = shm[1024 + h];
                float v2  = shv2[h];
                float hvA = fmaxf(spv + rowA[h], 0.f);
                float hvB = fmaxf(spv + rowB[h], 0.f);
                partA += hvA * v2;
                partB += hvB * v2;
            }
            #pragma unroll
            for (int off = 16; off > 0; off >>= 1) {
                partA += __shfl_xor_sync(0xffffffffu, partA, off);
                partB += __shfl_xor_sync(0xffffffffu, partB, off);
            }
            if (lane == 0) { shpart[w] = partA; shpart[w + 8] = partB; }
            __syncthreads();
            if (tid < 16) {
                float rho = 1.f / (1.f + expf(-(shpart[tid] + c2v)));
                shrho[tid] = rho;
                int ridx = (b * NSTEP + step) * MM + tid;
                out[rhoOff + ridx * rhoStride] = rho;
                if (rhoStride == 2) out[rhoOff + ridx * 2 + 1] = 0.f;
            }
            __syncthreads();
            if (tid == 0) {
                float rs = 0.f;
                #pragma unroll
                for (int m = 0; m < 16; m++) rs += shrho[m];
                g_rhosum[b] = rs;
            }
            const float* Ps = g_P + (size_t)step * P_STRIDE + (size_t)(b * 16) * HH;
            #pragma unroll
            for (int jj = 0; jj < 4; jj++) {
                int h = tid + 256 * jj;
                float sp1 = shm[h];
                float gacc = 0.f;
                #pragma unroll
                for (int m = 0; m < 16; m++) {
                    float hv = sp1 + Ps[(size_t)m * 1024 + h];
                    gacc += shrho[m] * fmaxf(hv, 0.f);
                }
                g_gT[h * 64 + b] = gacc;
            }
        }
        grid_bar(&sepoch);

        // ---- phase D: eta GEMM + phi update + s + next g_S (l-tile 4/block) ----
        if (bid < 64) {
            int l0 = bid * 4;
            const float4* wsrc = (const float4*)(g_W2T + ((size_t)step * 256 + l0) * 1024);
            #pragma unroll
            for (int r = 0; r < 4; r++)
                ((float4*)shm)[tid + 256 * r] = wsrc[tid + 256 * r];
            __syncthreads();
            int lloc = tid >> 6, b = tid & 63;
            int l = l0 + lloc;
            const float* wrow = shm + lloc * 1024;
            float acc = 0.f;
            #pragma unroll 8
            for (int k = 0; k < 1024; k++)
                acc += wrow[k] * g_gT[k * 64 + b];
            float eta = acc + g_rhosum[b] * b2[step * 256 + l];
            float phin = g_phi[b * 256 + l] - eta;
            g_phi[b * 256 + l] = phin;
            float sv, cv; sincosf(phin, &sv, &cv);
            write_s(out, (b * 11 + step + 1) * 256 + l, cv, sv, inter, imOff);
            g_S[l * 64 + b] = cv;
            g_S[(256 + l) * 64 + b] = sv;
        }
        grid_bar(&sepoch);
    }
}

// ============ launch ============
extern "C" void kernel_launch(void* const* d_in, const int* in_sizes, int n_in,
                              void* d_out, int out_size) {
    const float *phi=0,*wr=0,*wi=0,*yM=0,*W1=0,*b1=0,*W2=0,*b2=0,*V1=0,*c1=0,*V2=0,*c2=0;
    if (n_in == 12 && in_sizes[0] == 16384) {
        phi=(const float*)d_in[0]; wr=(const float*)d_in[1]; wi=(const float*)d_in[2];
        yM=(const float*)d_in[3];  W1=(const float*)d_in[4]; b1=(const float*)d_in[5];
        W2=(const float*)d_in[6];  b2=(const float*)d_in[7]; V1=(const float*)d_in[8];
        c1=(const float*)d_in[9];  V2=(const float*)d_in[10];c2=(const float*)d_in[11];
    } else {
        int seen262144 = 0, seen1024 = 0;
        for (int i = 0; i < n_in; i++) {
            const float* p = (const float*)d_in[i];
            switch (in_sizes[i]) {
                case 16384:    phi = p; break;
                case 4096:     yM  = p; break;
                case 13107200: W1  = p; break;
                case 10240:    b1  = p; break;
                case 2621440:  W2  = p; break;
                case 2560:     b2  = p; break;
                case 1310720:  V1  = p; break;
                case 1:        c2  = p; break;
                case 262144:   if (seen262144++ == 0) wr = p; else wi = p; break;
                case 1024:     if (seen1024++   == 0) c1 = p; else V2 = p; break;
                default: break;
            }
        }
    }
    float* out = (float*)d_out;

    // Output layout by out_size (validated: 190464 = real-cast layout)
    int inter = 0, imOff = -1, rhoOff = N_SELEM, rhoStride = 1;
    if (out_size == 370688)      { imOff = N_SELEM; rhoOff = 2 * N_SELEM; }
    else if (out_size == 380928) { inter = 1; imOff = -1; rhoOff = 2 * N_SELEM; rhoStride = 2; }

    // phi-independent precompute
    kTw  <<<2048, 256>>>(wr, wi);
    kTw2 <<<dim3(32, 8, 10), dim3(32, 8)>>>(W2);
    kY   <<<dim3(11, 8), 128>>>(yM, W1, V1);
    kGemmP<<<dim3(88, 8), 256>>>(W1, V1, b1, c1);

    // fused sequential chain (single persistent kernel)
    kReset<<<1, 1>>>();
    kChain<<<NB_CHAIN, 256>>>(phi, b2, V2, c2, W1, V1, out,
                              inter, imOff, rhoOff, rhoStride);
}

// round 7
// speedup vs baseline: 2.1248x; 1.7334x over previous
#include <cuda_runtime.h>
#include <math.h>

// Problem constants
#define B      64
#define LS     256
#define MM     16
#define NSTEP  10
#define HH     1024
#define BM     1024
#define KW     512
#define NSEG   11
#define P_STRIDE (BM*HH)

#define N_SELEM (B*(NSTEP+1)*LS)     // 180224
#define NB_CHAIN 128                 // chain grid (<=148 SMs -> co-resident)

// ---- scratch (static __device__, allocation-free) ----
__device__ float g_P[NSEG * BM * HH];
__device__ float g_Aw[BM * KW];
__device__ float g_W2T[NSTEP * LS * HH];
__device__ float g_WBT[NSTEP * 1024 * 512];   // [s][j][k] transposed W1 s-rows (20MB)
__device__ float g_VBT[1024 * 512];           // [j][k]   transposed V1 s-rows (2MB)
__device__ float g_yp[NSEG * MM * HH];
__device__ float g_phi[B * LS];
__device__ float g_S[2 * LS * B];            // [k][b]
__device__ float g_spart[B * 2048];          // [b][j]
__device__ float g_g[B * HH];                // [b][k]
__device__ float g_rhosum[B];

// grid-barrier state (reset each replay)
__device__ int g_arr[NB_CHAIN * 32];         // one flag per block, 128B apart
__device__ int g_rel;

__global__ void kReset() {
    int t = threadIdx.x;
    for (int i = t; i < NB_CHAIN * 32; i += 256) g_arr[i] = 0;
    if (t == 0) g_rel = 0;
}

__device__ __forceinline__ void grid_bar(int epoch) {
    __syncthreads();
    int bid = blockIdx.x, tid = threadIdx.x;
    if (bid == 0) {
        if (tid > 0 && tid < NB_CHAIN) {
            while (*(volatile int*)&g_arr[tid * 32] < epoch) { __nanosleep(32); }
        }
        __syncthreads();
        if (tid == 0) { __threadfence(); *(volatile int*)&g_rel = epoch; }
    } else {
        if (tid == 0) {
            __threadfence();
            *(volatile int*)&g_arr[bid * 32] = epoch;
            while (*(volatile int*)&g_rel < epoch) { __nanosleep(32); }
            __threadfence();
        }
    }
    __syncthreads();
}

__device__ __forceinline__ void write_s(float* out, int idx, float cv, float sv,
                                        int inter, int imOff) {
    if (inter) {
        out[2 * idx] = cv; out[2 * idx + 1] = sv;
    } else {
        out[idx] = cv;
        if (imOff >= 0) out[imOff + idx] = sv;
    }
}

// ============ precompute kernels ============

__global__ void kTw(const float* __restrict__ wr, const float* __restrict__ wi) {
    int e = blockIdx.x * 256 + threadIdx.x;
    int row = e >> 9, k = e & 511;
    int b = row >> 4, m = row & 15;
    float v = (k < 256) ? wr[((size_t)b * 256 + k) * 16 + m]
                        : wi[((size_t)b * 256 + (k - 256)) * 16 + m];
    g_Aw[e] = v;
}

__global__ void kTw2(const float* __restrict__ W2) {
    __shared__ float t[32][33];
    int s  = blockIdx.z;
    int k0 = blockIdx.x * 32, l0 = blockIdx.y * 32;
    int tx = threadIdx.x, ty = threadIdx.y;
    #pragma unroll
    for (int i = 0; i < 32; i += 8)
        t[ty + i][tx] = W2[((size_t)s * 1024 + k0 + ty + i) * 256 + l0 + tx];
    __syncthreads();
    #pragma unroll
    for (int i = 0; i < 32; i += 8)
        g_W2T[((size_t)s * 256 + l0 + ty + i) * 1024 + k0 + tx] = t[tx][ty + i];
}

// Transpose W1 s-rows / V1 s-rows into [j][k] for coalesced chain reads.
__global__ void kTwb(const float* __restrict__ W1, const float* __restrict__ V1) {
    __shared__ float t[32][33];
    int s  = blockIdx.z;                  // 0..10 (10 = V1)
    int j0 = blockIdx.x * 32;             // 32 tiles
    int k0 = blockIdx.y * 32;             // 16 tiles
    int tx = threadIdx.x, ty = threadIdx.y;   // 32 x 8
    #pragma unroll
    for (int i = 0; i < 32; i += 8) {
        int k = k0 + ty + i;
        float v = (s < NSTEP) ? W1[((size_t)s * 1280 + k) * 1024 + j0 + tx]
                              : V1[(size_t)k * 1024 + j0 + tx];
        t[ty + i][tx] = v;
    }
    __syncthreads();
    #pragma unroll
    for (int i = 0; i < 32; i += 8) {
        int j = j0 + ty + i;
        if (s < NSTEP)
            g_WBT[((size_t)s * 1024 + j) * 512 + k0 + tx] = t[tx][ty + i];
        else
            g_VBT[(size_t)j * 512 + k0 + tx] = t[tx][ty + i];
    }
}

__global__ void kY(const float* __restrict__ yM, const float* __restrict__ W1,
                   const float* __restrict__ V1) {
    __shared__ float sy[256 * 16];
    int s = blockIdx.x;
    int h = blockIdx.y * 128 + threadIdx.x;
    #pragma unroll
    for (int i = 0; i < 32; i++) sy[threadIdx.x + 128 * i] = yM[threadIdx.x + 128 * i];
    __syncthreads();
    const float* base = (s < NSTEP)
        ? (W1 + ((size_t)s * 1280 + 1024) * 1024 + h)
        : (V1 + (size_t)1024 * 1024 + h);
    float acc[16];
    #pragma unroll
    for (int m = 0; m < 16; m++) acc[m] = 0.f;
    #pragma unroll 4
    for (int l = 0; l < 256; l++) {
        float w = base[(size_t)l * 1024];
        #pragma unroll
        for (int m = 0; m < 16; m++) acc[m] += sy[l * 16 + m] * w;
    }
    #pragma unroll
    for (int m = 0; m < 16; m++) g_yp[((size_t)s * 16 + m) * HH + h] = acc[m];
}

// Big precompute GEMM (fp32, ~86% of FFMA roofline)
__global__ __launch_bounds__(256) void kGemmP(const float* __restrict__ W1,
                                              const float* __restrict__ V1,
                                              const float* __restrict__ b1,
                                              const float* __restrict__ c1) {
    __shared__ float sA[2][8][132];
    __shared__ float sB[2][8][128];
    int tid = threadIdx.x;
    int n0 = blockIdx.x * 128;
    int r0 = blockIdx.y * 128;
    int s = n0 >> 10;
    int hbase = n0 & 1023;
    const float* Bbase = (s < NSTEP)
        ? (W1 + ((size_t)s * 1280 + 512) * 1024 + hbase)
        : (V1 + (size_t)512 * 1024 + hbase);

    int a_row = tid >> 1;
    int a_k   = (tid & 1) * 4;
    int b_k   = tid >> 5;
    int b_col = (tid & 31) * 4;
    int tx = tid & 15, ty = tid >> 4;

    const float* Aptr = g_Aw + (size_t)(r0 + a_row) * KW + a_k;
    const float* Bptr = Bbase + (size_t)b_k * 1024 + b_col;

    float acc[8][8];
    #pragma unroll
    for (int i = 0; i < 8; i++)
        #pragma unroll
        for (int j = 0; j < 8; j++) acc[i][j] = 0.f;

    float4 ga = *(const float4*)(Aptr);
    float4 gb = *(const float4*)(Bptr);
    sA[0][a_k + 0][a_row] = ga.x; sA[0][a_k + 1][a_row] = ga.y;
    sA[0][a_k + 2][a_row] = ga.z; sA[0][a_k + 3][a_row] = ga.w;
    *(float4*)&sB[0][b_k][b_col] = gb;
    __syncthreads();

    int buf = 0;
    for (int kt = 0; kt < 64; kt++) {
        float4 na, nb;
        if (kt < 63) {
            int kn = (kt + 1) * 8;
            na = *(const float4*)(Aptr + kn);
            nb = *(const float4*)(Bptr + (size_t)kn * 1024);
        }
        #pragma unroll
        for (int kk = 0; kk < 8; kk++) {
            float a[8], bv[8];
            *(float4*)&a[0]  = *(const float4*)&sA[buf][kk][ty * 8];
            *(float4*)&a[4]  = *(const float4*)&sA[buf][kk][ty * 8 + 4];
            *(float4*)&bv[0] = *(const float4*)&sB[buf][kk][tx * 8];
            *(float4*)&bv[4] = *(const float4*)&sB[buf][kk][tx * 8 + 4];
            #pragma unroll
            for (int i = 0; i < 8; i++)
                #pragma unroll
                for (int j = 0; j < 8; j++) acc[i][j] += a[i] * bv[j];
        }
        if (kt < 63) {
            int nbf = buf ^ 1;
            sA[nbf][a_k + 0][a_row] = na.x; sA[nbf][a_k + 1][a_row] = na.y;
            sA[nbf][a_k + 2][a_row] = na.z; sA[nbf][a_k + 3][a_row] = na.w;
            *(float4*)&sB[nbf][b_k][b_col] = nb;
            __syncthreads();
            buf = nbf;
        }
    }

    const float* bias = (s < NSTEP) ? (b1 + s * 1024) : c1;
    #pragma unroll
    for (int i = 0; i < 8; i++) {
        int row = r0 + ty * 8 + i;
        int m = row & 15;
        float* dst        = g_P  + (size_t)s * P_STRIDE + (size_t)row * HH + hbase + tx * 8;
        const float* ypp  = g_yp + ((size_t)s * 16 + m) * HH + hbase + tx * 8;
        const float* bp   = bias + hbase + tx * 8;
        #pragma unroll
        for (int j = 0; j < 8; j++) dst[j] = acc[i][j] + ypp[j] + bp[j];
    }
}

// ============ fused sequential chain ============
__global__ __launch_bounds__(256) void kChain(
    const float* __restrict__ phi_in, const float* __restrict__ b2,
    const float* __restrict__ V2, const float* __restrict__ c2,
    float* __restrict__ out, int inter, int imOff, int rhoOff, int rhoStride)
{
    __shared__ float sw[16 * 516];   // 33KB: phase B weights (padded rows)
    __shared__ float shB[2048];      // 8KB : B S-chunk / C spart / D W2 rows
    __shared__ float shv2[1024];     // 4KB
    __shared__ float sEta[128];
    __shared__ float shpart[16];
    __shared__ float shrho[16];

    int tid = threadIdx.x, bid = blockIdx.x;
    int epoch = 0;
    #pragma unroll
    for (int i = 0; i < 4; i++) shv2[tid + 256 * i] = V2[tid + 256 * i];
    float c2v = c2[0];

    // ---- phase A0 ----
    if (bid < 64) {
        int b = bid, l = tid;
        float p = phi_in[b * 256 + l];
        g_phi[b * 256 + l] = p;
        float sv, cv; sincosf(p, &sv, &cv);
        write_s(out, (b * 11) * 256 + l, cv, sv, inter, imOff);
        g_S[l * 64 + b] = cv;
        g_S[(256 + l) * 64 + b] = sv;
    }
    grid_bar(++epoch);

    for (int step = 0; step < NSTEP; step++) {
        // ---- phase B: spart[b][j] = sum_k S[k][b] * W[j][k] (WBT coalesced) ----
        {
            int j0 = bid * 16;
            const float* wsrc = (j0 < 1024)
                ? (g_WBT + ((size_t)step * 1024 + j0) * 512)
                : (g_VBT + (size_t)(j0 - 1024) * 512);
            // stage 16x512 weights into smem (32KB contiguous, float4)
            #pragma unroll
            for (int r = 0; r < 8; r++) {
                int i = tid + 256 * r;            // f4 index < 2048
                int jj = i >> 7, kq = i & 127;
                float4 v = ((const float4*)wsrc)[i];
                *(float4*)&sw[jj * 516 + kq * 4] = v;
            }
            int jloc = tid & 15, b0 = (tid >> 4) * 4;
            int j = j0 + jloc;
            float a0 = 0.f, a1 = 0.f, a2 = 0.f, a3 = 0.f;
            const float* wrow = sw + jloc * 516;
            for (int kc = 0; kc < 16; kc++) {
                __syncthreads();
                // load S chunk [32 k][64 b] = 2048 floats
                const float4* src = (const float4*)(g_S + kc * 2048);
                ((float4*)shB)[tid]       = src[tid];
                ((float4*)shB)[tid + 256] = src[tid + 256];
                __syncthreads();
                #pragma unroll
                for (int kk = 0; kk < 32; kk++) {
                    float w = wrow[kc * 32 + kk];
                    float4 s4 = *(const float4*)&shB[kk * 64 + b0];
                    a0 += w * s4.x; a1 += w * s4.y; a2 += w * s4.z; a3 += w * s4.w;
                }
            }
            g_spart[(b0 + 0) * 2048 + j] = a0;
            g_spart[(b0 + 1) * 2048 + j] = a1;
            g_spart[(b0 + 2) * 2048 + j] = a2;
            g_spart[(b0 + 3) * 2048 + j] = a3;
        }
        grid_bar(++epoch);

        // ---- phase C: rho + g (per-b block) ----
        if (bid < 64) {
            int b = bid;
            const float4* sp4 = (const float4*)(g_spart + b * 2048);
            ((float4*)shB)[tid]       = sp4[tid];
            ((float4*)shB)[tid + 256] = sp4[tid + 256];
            __syncthreads();
            int w = tid >> 5, lane = tid & 31;
            const float* Pv = g_P + (size_t)NSTEP * P_STRIDE + (size_t)(b * 16) * HH;
            const float* rowA = Pv + (size_t)w * 1024;
            const float* rowB = Pv + (size_t)(w + 8) * 1024;
            float partA = 0.f, partB = 0.f;
            #pragma unroll 8
            for (int i = 0; i < 32; i++) {
                int h = lane + 32 * i;
                float spv = shB[1024 + h];
                float v2  = shv2[h];
                partA += fmaxf(spv + rowA[h], 0.f) * v2;
                partB += fmaxf(spv + rowB[h], 0.f) * v2;
            }
            #pragma unroll
            for (int off = 16; off > 0; off >>= 1) {
                partA += __shfl_xor_sync(0xffffffffu, partA, off);
                partB += __shfl_xor_sync(0xffffffffu, partB, off);
            }
            if (lane == 0) { shpart[w] = partA; shpart[w + 8] = partB; }
            __syncthreads();
            if (tid < 16) {
                float rho = 1.f / (1.f + expf(-(shpart[tid] + c2v)));
                shrho[tid] = rho;
                int ridx = (b * NSTEP + step) * MM + tid;
                out[rhoOff + ridx * rhoStride] = rho;
                if (rhoStride == 2) out[rhoOff + ridx * 2 + 1] = 0.f;
            }
            __syncthreads();
            if (tid == 0) {
                float rs = 0.f;
                #pragma unroll
                for (int m = 0; m < 16; m++) rs += shrho[m];
                g_rhosum[b] = rs;
            }
            const float* Ps = g_P + (size_t)step * P_STRIDE + (size_t)(b * 16) * HH;
            #pragma unroll
            for (int jj = 0; jj < 4; jj++) {
                int h = tid + 256 * jj;
                float sp1 = shB[h];
                float gacc = 0.f;
                #pragma unroll
                for (int m = 0; m < 16; m++)
                    gacc += shrho[m] * fmaxf(sp1 + Ps[(size_t)m * 1024 + h], 0.f);
                g_g[b * 1024 + h] = gacc;        // coalesced
            }
        }
        grid_bar(++epoch);

        // ---- phase D: eta + phi update (all 128 blocks, warp-per-(l,b) dots) ----
        {
            int l0 = bid * 2;
            const float4* wsrc = (const float4*)(g_W2T + ((size_t)step * 256 + l0) * 1024);
            ((float4*)shB)[tid]       = wsrc[tid];
            ((float4*)shB)[tid + 256] = wsrc[tid + 256];
            __syncthreads();
            int w = tid >> 5, lane = tid & 31;
            #pragma unroll
            for (int pi = 0; pi < 16; pi++) {
                int pp = w * 16 + pi;
                int lp = pp >> 6, b = pp & 63;
                const float* gr = g_g + b * 1024 + lane;
                const float* wr2 = shB + lp * 1024 + lane;
                float acc = 0.f;
                #pragma unroll
                for (int i = 0; i < 32; i++)
                    acc += wr2[32 * i] * gr[32 * i];
                #pragma unroll
                for (int off = 16; off > 0; off >>= 1)
                    acc += __shfl_xor_sync(0xffffffffu, acc, off);
                if (lane == 0) sEta[pp] = acc;
            }
            __syncthreads();
            if (tid < 128) {
                int lp = tid >> 6, b = tid & 63;
                int l = l0 + lp;
                float eta = sEta[tid] + g_rhosum[b] * b2[step * 256 + l];
                float phin = g_phi[b * 256 + l] - eta;
                g_phi[b * 256 + l] = phin;
                float sv, cv; sincosf(phin, &sv, &cv);
                write_s(out, (b * 11 + step + 1) * 256 + l, cv, sv, inter, imOff);
                g_S[l * 64 + b] = cv;
                g_S[(256 + l) * 64 + b] = sv;
            }
        }
        grid_bar(++epoch);
    }
}

// ============ launch ============
extern "C" void kernel_launch(void* const* d_in, const int* in_sizes, int n_in,
                              void* d_out, int out_size) {
    const float *phi=0,*wr=0,*wi=0,*yM=0,*W1=0,*b1=0,*W2=0,*b2=0,*V1=0,*c1=0,*V2=0,*c2=0;
    if (n_in == 12 && in_sizes[0] == 16384) {
        phi=(const float*)d_in[0]; wr=(const float*)d_in[1]; wi=(const float*)d_in[2];
        yM=(const float*)d_in[3];  W1=(const float*)d_in[4]; b1=(const float*)d_in[5];
        W2=(const float*)d_in[6];  b2=(const float*)d_in[7]; V1=(const float*)d_in[8];
        c1=(const float*)d_in[9];  V2=(const float*)d_in[10];c2=(const float*)d_in[11];
    } else {
        int seen262144 = 0, seen1024 = 0;
        for (int i = 0; i < n_in; i++) {
            const float* p = (const float*)d_in[i];
            switch (in_sizes[i]) {
                case 16384:    phi = p; break;
                case 4096:     yM  = p; break;
                case 13107200: W1  = p; break;
                case 10240:    b1  = p; break;
                case 2621440:  W2  = p; break;
                case 2560:     b2  = p; break;
                case 1310720:  V1  = p; break;
                case 1:        c2  = p; break;
                case 262144:   if (seen262144++ == 0) wr = p; else wi = p; break;
                case 1024:     if (seen1024++   == 0) c1 = p; else V2 = p; break;
                default: break;
            }
        }
    }
    float* out = (float*)d_out;

    int inter = 0, imOff = -1, rhoOff = N_SELEM, rhoStride = 1;
    if (out_size == 370688)      { imOff = N_SELEM; rhoOff = 2 * N_SELEM; }
    else if (out_size == 380928) { inter = 1; imOff = -1; rhoOff = 2 * N_SELEM; rhoStride = 2; }

    // phi-independent precompute
    kTw  <<<2048, 256>>>(wr, wi);
    kTw2 <<<dim3(32, 8, 10), dim3(32, 8)>>>(W2);
    kTwb <<<dim3(32, 16, 11), dim3(32, 8)>>>(W1, V1);
    kY   <<<dim3(11, 8), 128>>>(yM, W1, V1);
    kGemmP<<<dim3(88, 8), 256>>>(W1, V1, b1, c1);

    // fused sequential chain
    kReset<<<1, 256>>>();
    kChain<<<NB_CHAIN, 256>>>(phi, b2, V2, c2, out, inter, imOff, rhoOff, rhoStride);
}

// round 10
// speedup vs baseline: 2.8447x; 1.3388x over previous
#include <cuda_runtime.h>
#include <cuda_bf16.h>
#include <stdint.h>
#include <math.h>

// Problem constants
#define B      64
#define LS     256
#define MM     16
#define NSTEP  10
#define HH     1024
#define BM     1024
#define KW     512
#define NSEG   11
#define P_STRIDE (BM*HH)

#define N_SELEM (B*(NSTEP+1)*LS)     // 180224
#define NB_CHAIN 128

// GEMM tiling
#define PITCH 72                      // smem row pitch in bf16 (64 + 8 pad)
#define STAGE_ELEMS (128 * PITCH)     // per-matrix stage elems

// ---- scratch (static __device__, allocation-free) ----
__device__ float g_P[NSEG * BM * HH];
__device__ float g_W2T[NSTEP * LS * HH];
__device__ float g_WBT[NSTEP * 1024 * 512];
__device__ float g_VBT[1024 * 512];
__device__ float g_yp[NSEG * MM * HH];
__device__ float g_phi[B * LS];
__device__ float g_S[2 * LS * B];
__device__ float g_spart[B * 2048];
__device__ float g_g[B * HH];
__device__ float g_rhosum[B];

// split-bf16 GEMM operands
__device__ __nv_bfloat16 g_Abf[1024 * 1024];     // [m][k']: k'<512 hi, else lo
__device__ __nv_bfloat16 g_Wbf[11264 * 1024];    // [n][k']: k'<512 hi, else lo

// grid-barrier state
__device__ int g_arr[NB_CHAIN * 32];
__device__ int g_rel;

__global__ void kReset() {
    int t = threadIdx.x;
    for (int i = t; i < NB_CHAIN * 32; i += 256) g_arr[i] = 0;
    if (t == 0) g_rel = 0;
}

__device__ __forceinline__ void grid_bar(int epoch) {
    __syncthreads();
    int bid = blockIdx.x, tid = threadIdx.x;
    if (bid == 0) {
        if (tid > 0 && tid < NB_CHAIN) {
            while (*(volatile int*)&g_arr[tid * 32] < epoch) { __nanosleep(32); }
        }
        __syncthreads();
        if (tid == 0) { __threadfence(); *(volatile int*)&g_rel = epoch; }
    } else {
        if (tid == 0) {
            __threadfence();
            *(volatile int*)&g_arr[bid * 32] = epoch;
            while (*(volatile int*)&g_rel < epoch) { __nanosleep(32); }
            __threadfence();
        }
    }
    __syncthreads();
}

__device__ __forceinline__ void write_s(float* out, int idx, float cv, float sv,
                                        int inter, int imOff) {
    if (inter) { out[2 * idx] = cv; out[2 * idx + 1] = sv; }
    else { out[idx] = cv; if (imOff >= 0) out[imOff + idx] = sv; }
}

// ============ portable async-copy helpers (sm_80+; no 'a'-suffix features) ====
__device__ __forceinline__ uint32_t smem_u32(const void* p) {
    uint32_t a;
    asm("{ .reg .u64 t; cvta.to.shared.u64 t, %1; cvt.u32.u64 %0, t; }"
        : "=r"(a) : "l"(p));
    return a;
}
__device__ __forceinline__ void cp_async16(uint32_t dst, const void* src) {
    asm volatile("cp.async.cg.shared.global [%0], [%1], 16;" :: "r"(dst), "l"(src));
}
#define CP_COMMIT() asm volatile("cp.async.commit_group;" ::: "memory")
#define CP_WAIT0()  asm volatile("cp.async.wait_group 0;" ::: "memory")
#define CP_WAIT1()  asm volatile("cp.async.wait_group 1;" ::: "memory")

__device__ __forceinline__ void mma_bf16(float& c0, float& c1, float& c2, float& c3,
                                         uint32_t a0, uint32_t a1, uint32_t a2, uint32_t a3,
                                         uint32_t b0, uint32_t b1) {
    asm volatile(
        "mma.sync.aligned.m16n8k16.row.col.f32.bf16.bf16.f32 "
        "{%0,%1,%2,%3}, {%4,%5,%6,%7}, {%8,%9}, {%0,%1,%2,%3};"
        : "+f"(c0), "+f"(c1), "+f"(c2), "+f"(c3)
        : "r"(a0), "r"(a1), "r"(a2), "r"(a3), "r"(b0), "r"(b1));
}

// ============ precompute ============

// A split: [row][k] hi, [row][512+k] lo
__global__ void kConvA(const float* __restrict__ wr, const float* __restrict__ wi) {
    int e = blockIdx.x * 256 + threadIdx.x;       // 524288
    int row = e >> 9, k = e & 511;
    int b = row >> 4, m = row & 15;
    float a = (k < 256) ? wr[((size_t)b * 256 + k) * 16 + m]
                        : wi[((size_t)b * 256 + (k - 256)) * 16 + m];
    __nv_bfloat16 hi = __float2bfloat16(a);
    __nv_bfloat16 lo = __float2bfloat16(a - __bfloat162float(hi));
    g_Abf[(size_t)row * 1024 + k] = hi;
    g_Abf[(size_t)row * 1024 + 512 + k] = lo;
}

// W split + transpose: g_Wbf[n= s*1024+h][k] = hi(W[512+k][h]), [n][512+k] = lo
__global__ void kConvW(const float* __restrict__ W1, const float* __restrict__ V1) {
    __shared__ float t[32][33];
    int s  = blockIdx.z;
    int h0 = blockIdx.x * 32;
    int k0 = blockIdx.y * 32;
    int tx = threadIdx.x, ty = threadIdx.y;   // 32 x 8
    #pragma unroll
    for (int i = 0; i < 32; i += 8) {
        int k = k0 + ty + i;
        float v = (s < NSTEP) ? W1[((size_t)s * 1280 + 512 + k) * 1024 + h0 + tx]
                              : V1[(size_t)(512 + k) * 1024 + h0 + tx];
        t[ty + i][tx] = v;
    }
    __syncthreads();
    #pragma unroll
    for (int i = 0; i < 32; i += 8) {
        size_t n = (size_t)s * 1024 + h0 + ty + i;
        float a = t[tx][ty + i];
        __nv_bfloat16 hi = __float2bfloat16(a);
        __nv_bfloat16 lo = __float2bfloat16(a - __bfloat162float(hi));
        g_Wbf[n * 1024 + k0 + tx] = hi;
        g_Wbf[n * 1024 + 512 + k0 + tx] = lo;
    }
}

__global__ void kTw2(const float* __restrict__ W2) {
    __shared__ float t[32][33];
    int s  = blockIdx.z;
    int k0 = blockIdx.x * 32, l0 = blockIdx.y * 32;
    int tx = threadIdx.x, ty = threadIdx.y;
    #pragma unroll
    for (int i = 0; i < 32; i += 8)
        t[ty + i][tx] = W2[((size_t)s * 1024 + k0 + ty + i) * 256 + l0 + tx];
    __syncthreads();
    #pragma unroll
    for (int i = 0; i < 32; i += 8)
        g_W2T[((size_t)s * 256 + l0 + ty + i) * 1024 + k0 + tx] = t[tx][ty + i];
}

__global__ void kTwb(const float* __restrict__ W1, const float* __restrict__ V1) {
    __shared__ float t[32][33];
    int s  = blockIdx.z;
    int j0 = blockIdx.x * 32;
    int k0 = blockIdx.y * 32;
    int tx = threadIdx.x, ty = threadIdx.y;
    #pragma unroll
    for (int i = 0; i < 32; i += 8) {
        int k = k0 + ty + i;
        float v = (s < NSTEP) ? W1[((size_t)s * 1280 + k) * 1024 + j0 + tx]
                              : V1[(size_t)k * 1024 + j0 + tx];
        t[ty + i][tx] = v;
    }
    __syncthreads();
    #pragma unroll
    for (int i = 0; i < 32; i += 8) {
        int j = j0 + ty + i;
        if (s < NSTEP)
            g_WBT[((size_t)s * 1024 + j) * 512 + k0 + tx] = t[tx][ty + i];
        else
            g_VBT[(size_t)j * 512 + k0 + tx] = t[tx][ty + i];
    }
}

__global__ void kY(const float* __restrict__ yM, const float* __restrict__ W1,
                   const float* __restrict__ V1) {
    __shared__ float sy[256 * 16];
    int s = blockIdx.x;
    int h = blockIdx.y * 128 + threadIdx.x;
    #pragma unroll
    for (int i = 0; i < 32; i++) sy[threadIdx.x + 128 * i] = yM[threadIdx.x + 128 * i];
    __syncthreads();
    const float* base = (s < NSTEP)
        ? (W1 + ((size_t)s * 1280 + 1024) * 1024 + h)
        : (V1 + (size_t)1024 * 1024 + h);
    float acc[16];
    #pragma unroll
    for (int m = 0; m < 16; m++) acc[m] = 0.f;
    #pragma unroll 4
    for (int l = 0; l < 256; l++) {
        float w = base[(size_t)l * 1024];
        #pragma unroll
        for (int m = 0; m < 16; m++) acc[m] += sy[l * 16 + m] * w;
    }
    #pragma unroll
    for (int m = 0; m < 16; m++) g_yp[((size_t)s * 16 + m) * HH + h] = acc[m];
}

// ====== mma.sync split-bf16 GEMM: P = A' @ W'^T (+ yp + bias) ======
// grid (88, 8), 256 threads = 8 warps (2m x 4n), warp tile 64x32.
// 24 K-chunks of 64: term t2 = st/8: (aOff,wOff) = (0,0), (0,512), (512,0).
__global__ __launch_bounds__(256)
void kGemmT(const float* __restrict__ b1, const float* __restrict__ c1) {
    extern __shared__ __align__(16) __nv_bfloat16 sh[];   // 2 bufs x (A|B)

    int tid = threadIdx.x, wid = tid >> 5, lane = tid & 31;
    int warp_m = wid >> 2, warp_n = wid & 3;              // 2 x 4
    int n0 = blockIdx.x * 128;
    int r0 = blockIdx.y * 128;
    int g = lane >> 2, t4 = lane & 3;

    const __nv_bfloat16* agp = g_Abf + (size_t)r0 * 1024;
    const __nv_bfloat16* wgp = g_Wbf + (size_t)n0 * 1024;

    float c[4][4][4];
    #pragma unroll
    for (int mi = 0; mi < 4; mi++)
        #pragma unroll
        for (int ni = 0; ni < 4; ni++)
            #pragma unroll
            for (int q = 0; q < 4; q++) c[mi][ni][q] = 0.f;

    // stage loader: 64-col chunk of A and W into buffer
    auto load_stage = [&](int buf, int st) {
        int t2 = st >> 3, kc = st & 7;
        int aCol = ((t2 == 2) ? 512 : 0) + kc * 64;
        int wCol = ((t2 == 1) ? 512 : 0) + kc * 64;
        __nv_bfloat16* As = sh + (size_t)buf * 2 * STAGE_ELEMS;
        __nv_bfloat16* Bs = As + STAGE_ELEMS;
        #pragma unroll
        for (int r = 0; r < 4; r++) {
            int idx = tid + 256 * r;          // 0..1023
            int row = idx >> 3, c8 = idx & 7;
            cp_async16(smem_u32(As + row * PITCH + c8 * 8),
                       agp + (size_t)row * 1024 + aCol + c8 * 8);
            cp_async16(smem_u32(Bs + row * PITCH + c8 * 8),
                       wgp + (size_t)row * 1024 + wCol + c8 * 8);
        }
    };

    load_stage(0, 0);
    CP_COMMIT();

    int buf = 0;
    for (int st = 0; st < 24; st++) {
        if (st < 23) { load_stage(buf ^ 1, st + 1); CP_COMMIT(); CP_WAIT1(); }
        else         { CP_WAIT0(); }
        __syncthreads();

        const __nv_bfloat16* As = sh + (size_t)buf * 2 * STAGE_ELEMS;
        const __nv_bfloat16* Bs = As + STAGE_ELEMS;
        #pragma unroll
        for (int ks = 0; ks < 4; ks++) {
            uint32_t af[4][4], bf[4][2];
            #pragma unroll
            for (int mi = 0; mi < 4; mi++) {
                const __nv_bfloat16* ap =
                    As + (warp_m * 64 + mi * 16 + g) * PITCH + ks * 16 + 2 * t4;
                af[mi][0] = *(const uint32_t*)ap;
                af[mi][1] = *(const uint32_t*)(ap + 8 * PITCH);
                af[mi][2] = *(const uint32_t*)(ap + 8);
                af[mi][3] = *(const uint32_t*)(ap + 8 * PITCH + 8);
            }
            #pragma unroll
            for (int ni = 0; ni < 4; ni++) {
                const __nv_bfloat16* bp =
                    Bs + (warp_n * 32 + ni * 8 + g) * PITCH + ks * 16 + 2 * t4;
                bf[ni][0] = *(const uint32_t*)bp;
                bf[ni][1] = *(const uint32_t*)(bp + 8);
            }
            #pragma unroll
            for (int mi = 0; mi < 4; mi++)
                #pragma unroll
                for (int ni = 0; ni < 4; ni++)
                    mma_bf16(c[mi][ni][0], c[mi][ni][1], c[mi][ni][2], c[mi][ni][3],
                             af[mi][0], af[mi][1], af[mi][2], af[mi][3],
                             bf[ni][0], bf[ni][1]);
        }
        __syncthreads();
        buf ^= 1;
    }

    // epilogue: c[mi][ni] fragment -> g_P with yp + bias
    int s = n0 >> 10, hbase = n0 & 1023;
    const float* bias = (s < NSTEP) ? (b1 + s * 1024) : c1;
    #pragma unroll
    for (int mi = 0; mi < 4; mi++) {
        int rloc0 = warp_m * 64 + mi * 16 + g;        // and +8
        #pragma unroll
        for (int ni = 0; ni < 4; ni++) {
            int col = warp_n * 32 + ni * 8 + 2 * t4;  // even
            int hg = hbase + col;
            float yb0a = g_yp[((size_t)s * 16 + (rloc0 & 15)) * 1024 + hg]     + bias[hg];
            float yb1a = g_yp[((size_t)s * 16 + (rloc0 & 15)) * 1024 + hg + 1] + bias[hg + 1];
            int rloc1 = rloc0 + 8;
            float yb0b = g_yp[((size_t)s * 16 + (rloc1 & 15)) * 1024 + hg]     + bias[hg];
            float yb1b = g_yp[((size_t)s * 16 + (rloc1 & 15)) * 1024 + hg + 1] + bias[hg + 1];
            float2 v0; v0.x = c[mi][ni][0] + yb0a; v0.y = c[mi][ni][1] + yb1a;
            float2 v1; v1.x = c[mi][ni][2] + yb0b; v1.y = c[mi][ni][3] + yb1b;
            *(float2*)(g_P + (size_t)s * P_STRIDE + (size_t)(r0 + rloc0) * 1024 + hg) = v0;
            *(float2*)(g_P + (size_t)s * P_STRIDE + (size_t)(r0 + rloc1) * 1024 + hg) = v1;
        }
    }
}

// ============ fused sequential chain (unchanged from R7) ============
__global__ __launch_bounds__(256) void kChain(
    const float* __restrict__ phi_in, const float* __restrict__ b2,
    const float* __restrict__ V2, const float* __restrict__ c2,
    float* __restrict__ out, int inter, int imOff, int rhoOff, int rhoStride)
{
    __shared__ float sw[16 * 516];
    __shared__ float shB[2048];
    __shared__ float shv2[1024];
    __shared__ float sEta[128];
    __shared__ float shpart[16];
    __shared__ float shrho[16];

    int tid = threadIdx.x, bid = blockIdx.x;
    int epoch = 0;
    #pragma unroll
    for (int i = 0; i < 4; i++) shv2[tid + 256 * i] = V2[tid + 256 * i];
    float c2v = c2[0];

    if (bid < 64) {
        int b = bid, l = tid;
        float p = phi_in[b * 256 + l];
        g_phi[b * 256 + l] = p;
        float sv, cv; sincosf(p, &sv, &cv);
        write_s(out, (b * 11) * 256 + l, cv, sv, inter, imOff);
        g_S[l * 64 + b] = cv;
        g_S[(256 + l) * 64 + b] = sv;
    }
    grid_bar(++epoch);

    for (int step = 0; step < NSTEP; step++) {
        {
            int j0 = bid * 16;
            const float* wsrc = (j0 < 1024)
                ? (g_WBT + ((size_t)step * 1024 + j0) * 512)
                : (g_VBT + (size_t)(j0 - 1024) * 512);
            #pragma unroll
            for (int r = 0; r < 8; r++) {
                int i = tid + 256 * r;
                int jj = i >> 7, kq = i & 127;
                float4 v = ((const float4*)wsrc)[i];
                *(float4*)&sw[jj * 516 + kq * 4] = v;
            }
            int jloc = tid & 15, b0 = (tid >> 4) * 4;
            int j = j0 + jloc;
            float a0 = 0.f, a1 = 0.f, a2 = 0.f, a3 = 0.f;
            const float* wrow = sw + jloc * 516;
            for (int kc = 0; kc < 16; kc++) {
                __syncthreads();
                const float4* src = (const float4*)(g_S + kc * 2048);
                ((float4*)shB)[tid]       = src[tid];
                ((float4*)shB)[tid + 256] = src[tid + 256];
                __syncthreads();
                #pragma unroll
                for (int kk = 0; kk < 32; kk++) {
                    float w = wrow[kc * 32 + kk];
                    float4 s4 = *(const float4*)&shB[kk * 64 + b0];
                    a0 += w * s4.x; a1 += w * s4.y; a2 += w * s4.z; a3 += w * s4.w;
                }
            }
            g_spart[(b0 + 0) * 2048 + j] = a0;
            g_spart[(b0 + 1) * 2048 + j] = a1;
            g_spart[(b0 + 2) * 2048 + j] = a2;
            g_spart[(b0 + 3) * 2048 + j] = a3;
        }
        grid_bar(++epoch);

        if (bid < 64) {
            int b = bid;
            const float4* sp4 = (const float4*)(g_spart + b * 2048);
            ((float4*)shB)[tid]       = sp4[tid];
            ((float4*)shB)[tid + 256] = sp4[tid + 256];
            __syncthreads();
            int w = tid >> 5, lane = tid & 31;
            const float* Pv = g_P + (size_t)NSTEP * P_STRIDE + (size_t)(b * 16) * HH;
            const float* rowA = Pv + (size_t)w * 1024;
            const float* rowB = Pv + (size_t)(w + 8) * 1024;
            float partA = 0.f, partB = 0.f;
            #pragma unroll 8
            for (int i = 0; i < 32; i++) {
                int h = lane + 32 * i;
                float spv = shB[1024 + h];
                float v2  = shv2[h];
                partA += fmaxf(spv + rowA[h], 0.f) * v2;
                partB += fmaxf(spv + rowB[h], 0.f) * v2;
            }
            #pragma unroll
            for (int off = 16; off > 0; off >>= 1) {
                partA += __shfl_xor_sync(0xffffffffu, partA, off);
                partB += __shfl_xor_sync(0xffffffffu, partB, off);
            }
            if (lane == 0) { shpart[w] = partA; shpart[w + 8] = partB; }
            __syncthreads();
            if (tid < 16) {
                float rho = 1.f / (1.f + expf(-(shpart[tid] + c2v)));
                shrho[tid] = rho;
                int ridx = (b * NSTEP + step) * MM + tid;
                out[rhoOff + ridx * rhoStride] = rho;
                if (rhoStride == 2) out[rhoOff + ridx * 2 + 1] = 0.f;
            }
            __syncthreads();
            if (tid == 0) {
                float rs = 0.f;
                #pragma unroll
                for (int m = 0; m < 16; m++) rs += shrho[m];
                g_rhosum[b] = rs;
            }
            const float* Ps = g_P + (size_t)step * P_STRIDE + (size_t)(b * 16) * HH;
            #pragma unroll
            for (int jj = 0; jj < 4; jj++) {
                int h = tid + 256 * jj;
                float sp1 = shB[h];
                float gacc = 0.f;
                #pragma unroll
                for (int m = 0; m < 16; m++)
                    gacc += shrho[m] * fmaxf(sp1 + Ps[(size_t)m * 1024 + h], 0.f);
                g_g[b * 1024 + h] = gacc;
            }
        }
        grid_bar(++epoch);

        {
            int l0 = bid * 2;
            const float4* wsrc = (const float4*)(g_W2T + ((size_t)step * 256 + l0) * 1024);
            ((float4*)shB)[tid]       = wsrc[tid];
            ((float4*)shB)[tid + 256] = wsrc[tid + 256];
            __syncthreads();
            int w = tid >> 5, lane = tid & 31;
            #pragma unroll
            for (int pi = 0; pi < 16; pi++) {
                int pp = w * 16 + pi;
                int lp = pp >> 6, b = pp & 63;
                const float* gr = g_g + b * 1024 + lane;
                const float* wr2 = shB + lp * 1024 + lane;
                float acc = 0.f;
                #pragma unroll
                for (int i = 0; i < 32; i++)
                    acc += wr2[32 * i] * gr[32 * i];
                #pragma unroll
                for (int off = 16; off > 0; off >>= 1)
                    acc += __shfl_xor_sync(0xffffffffu, acc, off);
                if (lane == 0) sEta[pp] = acc;
            }
            __syncthreads();
            if (tid < 128) {
                int lp = tid >> 6, b = tid & 63;
                int l = l0 + lp;
                float eta = sEta[tid] + g_rhosum[b] * b2[step * 256 + l];
                float phin = g_phi[b * 256 + l] - eta;
                g_phi[b * 256 + l] = phin;
                float sv, cv; sincosf(phin, &sv, &cv);
                write_s(out, (b * 11 + step + 1) * 256 + l, cv, sv, inter, imOff);
                g_S[l * 64 + b] = cv;
                g_S[(256 + l) * 64 + b] = sv;
            }
        }
        grid_bar(++epoch);
    }
}

// ============ launch ============
extern "C" void kernel_launch(void* const* d_in, const int* in_sizes, int n_in,
                              void* d_out, int out_size) {
    const float *phi=0,*wr=0,*wi=0,*yM=0,*W1=0,*b1=0,*W2=0,*b2=0,*V1=0,*c1=0,*V2=0,*c2=0;
    if (n_in == 12 && in_sizes[0] == 16384) {
        phi=(const float*)d_in[0]; wr=(const float*)d_in[1]; wi=(const float*)d_in[2];
        yM=(const float*)d_in[3];  W1=(const float*)d_in[4]; b1=(const float*)d_in[5];
        W2=(const float*)d_in[6];  b2=(const float*)d_in[7]; V1=(const float*)d_in[8];
        c1=(const float*)d_in[9];  V2=(const float*)d_in[10];c2=(const float*)d_in[11];
    } else {
        int seen262144 = 0, seen1024 = 0;
        for (int i = 0; i < n_in; i++) {
            const float* p = (const float*)d_in[i];
            switch (in_sizes[i]) {
                case 16384:    phi = p; break;
                case 4096:     yM  = p; break;
                case 13107200: W1  = p; break;
                case 10240:    b1  = p; break;
                case 2621440:  W2  = p; break;
                case 2560:     b2  = p; break;
                case 1310720:  V1  = p; break;
                case 1:        c2  = p; break;
                case 262144:   if (seen262144++ == 0) wr = p; else wi = p; break;
                case 1024:     if (seen1024++   == 0) c1 = p; else V2 = p; break;
                default: break;
            }
        }
    }
    float* out = (float*)d_out;

    int inter = 0, imOff = -1, rhoOff = N_SELEM, rhoStride = 1;
    if (out_size == 370688)      { imOff = N_SELEM; rhoOff = 2 * N_SELEM; }
    else if (out_size == 380928) { inter = 1; imOff = -1; rhoOff = 2 * N_SELEM; rhoStride = 2; }

    const int GEMM_SMEM = 2 * 2 * STAGE_ELEMS * (int)sizeof(__nv_bfloat16);  // 73728
    static int smem_set = 0;
    if (!smem_set) {
        cudaFuncSetAttribute(kGemmT, cudaFuncAttributeMaxDynamicSharedMemorySize, GEMM_SMEM);
        smem_set = 1;
    }

    // phi-independent precompute
    kTw2  <<<dim3(32, 8, 10), dim3(32, 8)>>>(W2);
    kTwb  <<<dim3(32, 16, 11), dim3(32, 8)>>>(W1, V1);
    kY    <<<dim3(11, 8), 128>>>(yM, W1, V1);
    kConvA<<<2048, 256>>>(wr, wi);
    kConvW<<<dim3(32, 16, 11), dim3(32, 8)>>>(W1, V1);
    kGemmT<<<dim3(88, 8), 256, GEMM_SMEM>>>(b1, c1);

    // fused sequential chain
    kReset<<<1, 256>>>();
    kChain<<<NB_CHAIN, 256>>>(phi, b2, V2, c2, out, inter, imOff, rhoOff, rhoStride);
}